// round 13
// baseline (speedup 1.0000x reference)
#include <cuda_runtime.h>
#include <cuda_fp16.h>
#include <cstdint>

#define BN 16
#define QN 256
#define KN 256
#define DN 256
#define HN 256
#define TQ 4
#define H2 (HN/2)

// scratch (device globals: no allocation allowed) — both projections half,
// row-major [row][h] with h contiguous (q row = (b,q), k row = (b,kj)).
__device__ __half g_qproj[BN * QN * HN];
__device__ __half g_kproj[BN * KN * HN];

__device__ __forceinline__ __half2 htanh2(__half2 x) {
    unsigned r, xi = *(unsigned*)&x;
    asm("tanh.approx.f16x2 %0, %1;" : "=r"(r) : "r"(xi));
    return *(__half2*)&r;
}

// ---------------------------------------------------------------------------
// Kernel A: dual projection GEMM on tensor cores (m16n8k16 f16, f32 accum).
// Block tile 128x128, 8 warps of 32x64. (unchanged — verified at R8)
// ---------------------------------------------------------------------------
__global__ void __launch_bounds__(256, 1) proj_kernel(
    const float* __restrict__ Aq, const float* __restrict__ Ak,
    const float* __restrict__ Wq, const float* __restrict__ Wk)
{
    const int z = blockIdx.z;
    const float* __restrict__ A = z ? Ak : Aq;
    const float* __restrict__ W = z ? Wk : Wq;
    __half* __restrict__ out = z ? g_kproj : g_qproj;

    __shared__ __half As[128 * 24];   // [row][k] stride 24
    __shared__ __half Bs[128 * 24];   // [n][k]   stride 24 (transposed W tile)

    const int tid  = threadIdx.x;
    const int wid  = tid >> 5, lane = tid & 31;
    const int m0   = blockIdx.x * 128;
    const int n0   = blockIdx.y * 128;
    const int wm   = (wid & 3) * 32;
    const int wn   = (wid >> 2) * 64;

    const int arow = tid >> 1, acol = (tid & 1) * 8;
    const int bk   = tid >> 4, bn   = (tid & 15) * 8;

    const uint32_t as_base = (uint32_t)__cvta_generic_to_shared(As);
    const uint32_t bs_base = (uint32_t)__cvta_generic_to_shared(Bs);

    float4 a0v = *(const float4*)&A[(m0 + arow) * 256 + acol];
    float4 a1v = *(const float4*)&A[(m0 + arow) * 256 + acol + 4];
    float4 b0v = *(const float4*)&W[bk * 256 + n0 + bn];
    float4 b1v = *(const float4*)&W[bk * 256 + n0 + bn + 4];

    float acc[2][8][4];
#pragma unroll
    for (int mi = 0; mi < 2; mi++)
#pragma unroll
        for (int ni = 0; ni < 8; ni++)
#pragma unroll
            for (int t = 0; t < 4; t++) acc[mi][ni][t] = 0.f;

#pragma unroll 1
    for (int ks = 0; ks < 16; ks++) {
        {
            __half2 ah[4];
            ah[0] = __floats2half2_rn(a0v.x, a0v.y);
            ah[1] = __floats2half2_rn(a0v.z, a0v.w);
            ah[2] = __floats2half2_rn(a1v.x, a1v.y);
            ah[3] = __floats2half2_rn(a1v.z, a1v.w);
            *(uint4*)&As[arow * 24 + acol] = *(uint4*)ah;

            float bf[8] = {b0v.x, b0v.y, b0v.z, b0v.w,
                           b1v.x, b1v.y, b1v.z, b1v.w};
#pragma unroll
            for (int j = 0; j < 8; j++)
                Bs[(bn + j) * 24 + bk] = __float2half_rn(bf[j]);
        }
        __syncthreads();

        if (ks < 15) {
            const int kk = (ks + 1) * 16;
            a0v = *(const float4*)&A[(m0 + arow) * 256 + kk + acol];
            a1v = *(const float4*)&A[(m0 + arow) * 256 + kk + acol + 4];
            b0v = *(const float4*)&W[(kk + bk) * 256 + n0 + bn];
            b1v = *(const float4*)&W[(kk + bk) * 256 + n0 + bn + 4];
        }

        uint32_t af[2][4];
#pragma unroll
        for (int mi = 0; mi < 2; mi++) {
            uint32_t addr = as_base +
                ((wm + mi * 16 + (lane & 15)) * 24 + (lane >> 4) * 8) * 2;
            asm volatile(
                "ldmatrix.sync.aligned.m8n8.x4.shared.b16 {%0,%1,%2,%3}, [%4];"
                : "=r"(af[mi][0]), "=r"(af[mi][1]),
                  "=r"(af[mi][2]), "=r"(af[mi][3]) : "r"(addr));
        }
        uint32_t bf[8][2];
#pragma unroll
        for (int g = 0; g < 4; g++) {
            uint32_t addr = bs_base +
                ((wn + g * 16 + ((lane >> 4) << 3) + (lane & 7)) * 24 +
                 ((lane >> 3) & 1) * 8) * 2;
            uint32_t r0, r1, r2, r3;
            asm volatile(
                "ldmatrix.sync.aligned.m8n8.x4.shared.b16 {%0,%1,%2,%3}, [%4];"
                : "=r"(r0), "=r"(r1), "=r"(r2), "=r"(r3) : "r"(addr));
            bf[g * 2 + 0][0] = r0; bf[g * 2 + 0][1] = r1;
            bf[g * 2 + 1][0] = r2; bf[g * 2 + 1][1] = r3;
        }
#pragma unroll
        for (int mi = 0; mi < 2; mi++)
#pragma unroll
            for (int ni = 0; ni < 8; ni++) {
                asm volatile(
                    "mma.sync.aligned.m16n8k16.row.col.f32.f16.f16.f32 "
                    "{%0,%1,%2,%3}, {%4,%5,%6,%7}, {%8,%9}, {%0,%1,%2,%3};"
                    : "+f"(acc[mi][ni][0]), "+f"(acc[mi][ni][1]),
                      "+f"(acc[mi][ni][2]), "+f"(acc[mi][ni][3])
                    : "r"(af[mi][0]), "r"(af[mi][1]),
                      "r"(af[mi][2]), "r"(af[mi][3]),
                      "r"(bf[ni][0]), "r"(bf[ni][1]));
            }
        __syncthreads();
    }

#pragma unroll
    for (int mi = 0; mi < 2; mi++)
#pragma unroll
        for (int ni = 0; ni < 8; ni++) {
            const int row = m0 + wm + mi * 16 + (lane >> 2);
            const int col = n0 + wn + ni * 8 + (lane & 3) * 2;
            *(__half2*)&out[row * 256 + col] =
                __floats2half2_rn(acc[mi][ni][0], acc[mi][ni][1]);
            *(__half2*)&out[(row + 8) * 256 + col] =
                __floats2half2_rn(acc[mi][ni][2], acc[mi][ni][3]);
        }
}

// ---------------------------------------------------------------------------
// Kernel B: fused scores + mask + softmax + attn@V.
// R13: launch_bounds(256,6) -> <=42 regs -> 6 resident blocks/SM (~70% occ).
// AV double-buffer narrowed to 4-wide to fit the reg budget. Everything else
// as R12 (TQ=4, split fp16 accumulators, mask-skip, vlen-bounded AV).
// ---------------------------------------------------------------------------
__global__ void __launch_bounds__(256, 6) attn_kernel(
    const float* __restrict__ values, const int* __restrict__ vlens_i32,
    const float* __restrict__ wv, float* __restrict__ out)
{
    const int b  = blockIdx.y;
    const int q0 = blockIdx.x * TQ;
    const int tid = threadIdx.x;

    __shared__ __half2 q_s2[TQ][H2];                 // 2 KB
    __shared__ __align__(16) float s_s[TQ][KN];      // 4 KB
    __shared__ __half2 wv_s2[H2];                    // 0.5 KB

    // load q tile (already half) + wv
    const uint4* qbase = (const uint4*)(g_qproj + (b * QN + q0) * HN);
    for (int i = tid; i < TQ * H2 / 4; i += 256)
        ((uint4*)q_s2)[i] = qbase[i];
    for (int i = tid; i < H2; i += 256) {
        float2 v = ((const float2*)wv)[i];
        wv_s2[i] = __float22half2_rn(v);
    }
    __syncthreads();

    const int stride = (vlens_i32[1] == 0) ? 2 : 1;   // int64 vs int32 probe
    const int vlen = vlens_i32[b * stride];

    // ---- score phase: this thread owns column kj = tid ----
    const int kj = tid;
    float acc[TQ];
#pragma unroll
    for (int i = 0; i < TQ; i++) acc[i] = 0.f;

    if (kj < vlen) {
        const uint4* krow = (const uint4*)(g_kproj + (b * KN + kj) * HN);

        uint4 ka = __ldg(krow + 0), kb = __ldg(krow + 1);

#pragma unroll 1
        for (int c = 0; c < 32; c += 2) {            // 2 chunks (16 h) / iter
            const int nc = (c + 2 < 32) ? c + 2 : c;
            uint4 na = __ldg(krow + nc), nb = __ldg(krow + nc + 1);

            __half2 kva[4], kvb[4];
            kva[0] = *(__half2*)&ka.x; kva[1] = *(__half2*)&ka.y;
            kva[2] = *(__half2*)&ka.z; kva[3] = *(__half2*)&ka.w;
            kvb[0] = *(__half2*)&kb.x; kvb[1] = *(__half2*)&kb.y;
            kvb[2] = *(__half2*)&kb.z; kvb[3] = *(__half2*)&kb.w;

            const int hc2 = c * 4;
            __half2 wra[4], wrb[4];
#pragma unroll
            for (int t = 0; t < 4; t++) wra[t] = wv_s2[hc2 + t];
#pragma unroll
            for (int t = 0; t < 4; t++) wrb[t] = wv_s2[hc2 + 4 + t];

#pragma unroll
            for (int qi = 0; qi < TQ; qi++) {
                uint4 qra = *(const uint4*)&q_s2[qi][hc2];
                uint4 qrb = *(const uint4*)&q_s2[qi][hc2 + 4];
                __half2 qa[4], qb[4];
                qa[0] = *(__half2*)&qra.x; qa[1] = *(__half2*)&qra.y;
                qa[2] = *(__half2*)&qra.z; qa[3] = *(__half2*)&qra.w;
                qb[0] = *(__half2*)&qrb.x; qb[1] = *(__half2*)&qrb.y;
                qb[2] = *(__half2*)&qrb.z; qb[3] = *(__half2*)&qrb.w;

                // two independent fp16 accumulators -> half the HFMA2 chain
                __half2 a0 = __float2half2_rn(0.f);
                __half2 a1 = __float2half2_rn(0.f);
#pragma unroll
                for (int t = 0; t < 4; t++)
                    a0 = __hfma2(wra[t], htanh2(__hadd2(qa[t], kva[t])), a0);
#pragma unroll
                for (int t = 0; t < 4; t++)
                    a1 = __hfma2(wrb[t], htanh2(__hadd2(qb[t], kvb[t])), a1);
                float2 f0 = __half22float2(a0);
                float2 f1 = __half22float2(a1);
                acc[qi] += (f0.x + f0.y) + (f1.x + f1.y);
            }
            ka = na; kb = nb;
        }
    }

    // ---- mask + stash scores ----
    const bool live = (kj < vlen);
#pragma unroll
    for (int qi = 0; qi < TQ; qi++)
        s_s[qi][kj] = live ? acc[qi] : -1e6f;
    __syncthreads();

    // ---- softmax: warp w handles row w (warps 0..TQ-1) ----
    const int w = tid >> 5, lane = tid & 31;
    if (w < TQ) {
        const int r = w;
        float vals[8];
        float vmax = -1e30f;
#pragma unroll
        for (int t = 0; t < 8; t++) {
            vals[t] = s_s[r][lane + t * 32];
            vmax = fmaxf(vmax, vals[t]);
        }
#pragma unroll
        for (int off = 16; off; off >>= 1)
            vmax = fmaxf(vmax, __shfl_xor_sync(0xFFFFFFFFu, vmax, off));
        float vsum = 0.f;
#pragma unroll
        for (int t = 0; t < 8; t++) {
            vals[t] = __expf(vals[t] - vmax);
            vsum += vals[t];
        }
#pragma unroll
        for (int off = 16; off; off >>= 1)
            vsum += __shfl_xor_sync(0xFFFFFFFFu, vsum, off);
        const float inv = 1.f / vsum;
#pragma unroll
        for (int t = 0; t < 8; t++)
            s_s[r][lane + t * 32] = vals[t] * inv;
    }
    __syncthreads();

    // ---- attn @ values: thread owns column d = tid ----
    // 4-wide v double-buffer (reg budget); s_s rows read as float4;
    // k >= vlen skipped (attn weights there are exactly 0).
    const int d = tid;
    const int kend = (vlen + 3) & ~3;              // vlen >= 1 so kend >= 4
    const float* vb = values + b * KN * DN + d;
    float o[TQ];
#pragma unroll
    for (int i = 0; i < TQ; i++) o[i] = 0.f;

    float v[4], vn[4];
#pragma unroll
    for (int t = 0; t < 4; t++) v[t] = __ldg(vb + t * DN);

#pragma unroll 1
    for (int k = 0; k < kend; k += 4) {
        const int nk = (k + 4 < kend) ? k + 4 : k;
#pragma unroll
        for (int t = 0; t < 4; t++) vn[t] = __ldg(vb + (nk + t) * DN);
#pragma unroll
        for (int qi = 0; qi < TQ; qi++) {
            const float4 sa = *(const float4*)&s_s[qi][k];
            o[qi] += sa.x * v[0] + sa.y * v[1] + sa.z * v[2] + sa.w * v[3];
        }
#pragma unroll
        for (int t = 0; t < 4; t++) v[t] = vn[t];
    }
    float* ob = out + (b * QN + q0) * DN + d;
#pragma unroll
    for (int qi = 0; qi < TQ; qi++) ob[qi * DN] = o[qi];
}

// ---------------------------------------------------------------------------
extern "C" void kernel_launch(void* const* d_in, const int* in_sizes, int n_in,
                              void* d_out, int out_size)
{
    const float* queries = (const float*)d_in[0];
    const float* keys    = (const float*)d_in[1];
    const float* values  = (const float*)d_in[2];
    const int*   vlens   = (const int*)d_in[3];
    const float* Wq      = (const float*)d_in[4];
    const float* Wk      = (const float*)d_in[5];
    const float* wv      = (const float*)d_in[6];
    float*       out     = (float*)d_out;

    dim3 gA(32, 2, 2);               // (4096/128, 256/128, {q,k}) = 128 blocks
    proj_kernel<<<gA, 256>>>(queries, keys, Wq, Wk);

    dim3 gB(QN / TQ, BN);            // (64, 16) = 1024 blocks
    attn_kernel<<<gB, 256>>>(values, vlens, wv, out);
}

// round 14
// speedup vs baseline: 1.0534x; 1.0534x over previous
#include <cuda_runtime.h>
#include <cuda_fp16.h>
#include <cstdint>

#define BN 16
#define QN 256
#define KN 256
#define DN 256
#define HN 256
#define TQ 4
#define H2 (HN/2)

// scratch (device globals: no allocation allowed) — both projections half,
// row-major [row][h] with h contiguous (q row = (b,q), k row = (b,kj)).
__device__ __half g_qproj[BN * QN * HN];
__device__ __half g_kproj[BN * KN * HN];

__device__ __forceinline__ __half2 htanh2(__half2 x) {
    unsigned r, xi = *(unsigned*)&x;
    asm("tanh.approx.f16x2 %0, %1;" : "=r"(r) : "r"(xi));
    return *(__half2*)&r;
}

// ---------------------------------------------------------------------------
// Kernel A: dual projection GEMM on tensor cores (m16n8k16 f16, f32 accum).
// Block tile 128x128, 8 warps of 32x64. (unchanged — verified at R8)
// ---------------------------------------------------------------------------
__global__ void __launch_bounds__(256, 1) proj_kernel(
    const float* __restrict__ Aq, const float* __restrict__ Ak,
    const float* __restrict__ Wq, const float* __restrict__ Wk)
{
    const int z = blockIdx.z;
    const float* __restrict__ A = z ? Ak : Aq;
    const float* __restrict__ W = z ? Wk : Wq;
    __half* __restrict__ out = z ? g_kproj : g_qproj;

    __shared__ __half As[128 * 24];   // [row][k] stride 24
    __shared__ __half Bs[128 * 24];   // [n][k]   stride 24 (transposed W tile)

    const int tid  = threadIdx.x;
    const int wid  = tid >> 5, lane = tid & 31;
    const int m0   = blockIdx.x * 128;
    const int n0   = blockIdx.y * 128;
    const int wm   = (wid & 3) * 32;
    const int wn   = (wid >> 2) * 64;

    const int arow = tid >> 1, acol = (tid & 1) * 8;
    const int bk   = tid >> 4, bn   = (tid & 15) * 8;

    const uint32_t as_base = (uint32_t)__cvta_generic_to_shared(As);
    const uint32_t bs_base = (uint32_t)__cvta_generic_to_shared(Bs);

    float4 a0v = *(const float4*)&A[(m0 + arow) * 256 + acol];
    float4 a1v = *(const float4*)&A[(m0 + arow) * 256 + acol + 4];
    float4 b0v = *(const float4*)&W[bk * 256 + n0 + bn];
    float4 b1v = *(const float4*)&W[bk * 256 + n0 + bn + 4];

    float acc[2][8][4];
#pragma unroll
    for (int mi = 0; mi < 2; mi++)
#pragma unroll
        for (int ni = 0; ni < 8; ni++)
#pragma unroll
            for (int t = 0; t < 4; t++) acc[mi][ni][t] = 0.f;

#pragma unroll 1
    for (int ks = 0; ks < 16; ks++) {
        {
            __half2 ah[4];
            ah[0] = __floats2half2_rn(a0v.x, a0v.y);
            ah[1] = __floats2half2_rn(a0v.z, a0v.w);
            ah[2] = __floats2half2_rn(a1v.x, a1v.y);
            ah[3] = __floats2half2_rn(a1v.z, a1v.w);
            *(uint4*)&As[arow * 24 + acol] = *(uint4*)ah;

            float bf[8] = {b0v.x, b0v.y, b0v.z, b0v.w,
                           b1v.x, b1v.y, b1v.z, b1v.w};
#pragma unroll
            for (int j = 0; j < 8; j++)
                Bs[(bn + j) * 24 + bk] = __float2half_rn(bf[j]);
        }
        __syncthreads();

        if (ks < 15) {
            const int kk = (ks + 1) * 16;
            a0v = *(const float4*)&A[(m0 + arow) * 256 + kk + acol];
            a1v = *(const float4*)&A[(m0 + arow) * 256 + kk + acol + 4];
            b0v = *(const float4*)&W[(kk + bk) * 256 + n0 + bn];
            b1v = *(const float4*)&W[(kk + bk) * 256 + n0 + bn + 4];
        }

        uint32_t af[2][4];
#pragma unroll
        for (int mi = 0; mi < 2; mi++) {
            uint32_t addr = as_base +
                ((wm + mi * 16 + (lane & 15)) * 24 + (lane >> 4) * 8) * 2;
            asm volatile(
                "ldmatrix.sync.aligned.m8n8.x4.shared.b16 {%0,%1,%2,%3}, [%4];"
                : "=r"(af[mi][0]), "=r"(af[mi][1]),
                  "=r"(af[mi][2]), "=r"(af[mi][3]) : "r"(addr));
        }
        uint32_t bf[8][2];
#pragma unroll
        for (int g = 0; g < 4; g++) {
            uint32_t addr = bs_base +
                ((wn + g * 16 + ((lane >> 4) << 3) + (lane & 7)) * 24 +
                 ((lane >> 3) & 1) * 8) * 2;
            uint32_t r0, r1, r2, r3;
            asm volatile(
                "ldmatrix.sync.aligned.m8n8.x4.shared.b16 {%0,%1,%2,%3}, [%4];"
                : "=r"(r0), "=r"(r1), "=r"(r2), "=r"(r3) : "r"(addr));
            bf[g * 2 + 0][0] = r0; bf[g * 2 + 0][1] = r1;
            bf[g * 2 + 1][0] = r2; bf[g * 2 + 1][1] = r3;
        }
#pragma unroll
        for (int mi = 0; mi < 2; mi++)
#pragma unroll
            for (int ni = 0; ni < 8; ni++) {
                asm volatile(
                    "mma.sync.aligned.m16n8k16.row.col.f32.f16.f16.f32 "
                    "{%0,%1,%2,%3}, {%4,%5,%6,%7}, {%8,%9}, {%0,%1,%2,%3};"
                    : "+f"(acc[mi][ni][0]), "+f"(acc[mi][ni][1]),
                      "+f"(acc[mi][ni][2]), "+f"(acc[mi][ni][3])
                    : "r"(af[mi][0]), "r"(af[mi][1]),
                      "r"(af[mi][2]), "r"(af[mi][3]),
                      "r"(bf[ni][0]), "r"(bf[ni][1]));
            }
        __syncthreads();
    }

#pragma unroll
    for (int mi = 0; mi < 2; mi++)
#pragma unroll
        for (int ni = 0; ni < 8; ni++) {
            const int row = m0 + wm + mi * 16 + (lane >> 2);
            const int col = n0 + wn + ni * 8 + (lane & 3) * 2;
            *(__half2*)&out[row * 256 + col] =
                __floats2half2_rn(acc[mi][ni][0], acc[mi][ni][1]);
            *(__half2*)&out[(row + 8) * 256 + col] =
                __floats2half2_rn(acc[mi][ni][2], acc[mi][ni][3]);
        }
}

// ---------------------------------------------------------------------------
// Kernel B: fused scores + mask + softmax + attn@V.
// R14: launch_bounds(256,5) -> <=51 regs -> 5 resident blocks/SM, keeping
// R12's full 8-wide AV double-buffer and score structure (peak live ~50 regs
// fits). Probes the reg/occupancy midpoint between R12 (64r/4blk, best) and
// R13 (40r/6blk, regressed).
// ---------------------------------------------------------------------------
__global__ void __launch_bounds__(256, 5) attn_kernel(
    const float* __restrict__ values, const int* __restrict__ vlens_i32,
    const float* __restrict__ wv, float* __restrict__ out)
{
    const int b  = blockIdx.y;
    const int q0 = blockIdx.x * TQ;
    const int tid = threadIdx.x;

    __shared__ __half2 q_s2[TQ][H2];                 // 2 KB
    __shared__ __align__(16) float s_s[TQ][KN];      // 4 KB
    __shared__ __half2 wv_s2[H2];                    // 0.5 KB

    // load q tile (already half) + wv
    const uint4* qbase = (const uint4*)(g_qproj + (b * QN + q0) * HN);
    for (int i = tid; i < TQ * H2 / 4; i += 256)
        ((uint4*)q_s2)[i] = qbase[i];
    for (int i = tid; i < H2; i += 256) {
        float2 v = ((const float2*)wv)[i];
        wv_s2[i] = __float22half2_rn(v);
    }
    __syncthreads();

    const int stride = (vlens_i32[1] == 0) ? 2 : 1;   // int64 vs int32 probe
    const int vlen = vlens_i32[b * stride];

    // ---- score phase: this thread owns column kj = tid ----
    const int kj = tid;
    float acc[TQ];
#pragma unroll
    for (int i = 0; i < TQ; i++) acc[i] = 0.f;

    if (kj < vlen) {
        const uint4* krow = (const uint4*)(g_kproj + (b * KN + kj) * HN);

        uint4 ka = __ldg(krow + 0), kb = __ldg(krow + 1);

#pragma unroll 1
        for (int c = 0; c < 32; c += 2) {            // 2 chunks (16 h) / iter
            const int nc = (c + 2 < 32) ? c + 2 : c;
            uint4 na = __ldg(krow + nc), nb = __ldg(krow + nc + 1);

            __half2 kva[4], kvb[4];
            kva[0] = *(__half2*)&ka.x; kva[1] = *(__half2*)&ka.y;
            kva[2] = *(__half2*)&ka.z; kva[3] = *(__half2*)&ka.w;
            kvb[0] = *(__half2*)&kb.x; kvb[1] = *(__half2*)&kb.y;
            kvb[2] = *(__half2*)&kb.z; kvb[3] = *(__half2*)&kb.w;

            const int hc2 = c * 4;
            __half2 wra[4], wrb[4];
#pragma unroll
            for (int t = 0; t < 4; t++) wra[t] = wv_s2[hc2 + t];
#pragma unroll
            for (int t = 0; t < 4; t++) wrb[t] = wv_s2[hc2 + 4 + t];

#pragma unroll
            for (int qi = 0; qi < TQ; qi++) {
                uint4 qra = *(const uint4*)&q_s2[qi][hc2];
                uint4 qrb = *(const uint4*)&q_s2[qi][hc2 + 4];
                __half2 qa[4], qb[4];
                qa[0] = *(__half2*)&qra.x; qa[1] = *(__half2*)&qra.y;
                qa[2] = *(__half2*)&qra.z; qa[3] = *(__half2*)&qra.w;
                qb[0] = *(__half2*)&qrb.x; qb[1] = *(__half2*)&qrb.y;
                qb[2] = *(__half2*)&qrb.z; qb[3] = *(__half2*)&qrb.w;

                // two independent fp16 accumulators -> half the HFMA2 chain
                __half2 a0 = __float2half2_rn(0.f);
                __half2 a1 = __float2half2_rn(0.f);
#pragma unroll
                for (int t = 0; t < 4; t++)
                    a0 = __hfma2(wra[t], htanh2(__hadd2(qa[t], kva[t])), a0);
#pragma unroll
                for (int t = 0; t < 4; t++)
                    a1 = __hfma2(wrb[t], htanh2(__hadd2(qb[t], kvb[t])), a1);
                float2 f0 = __half22float2(a0);
                float2 f1 = __half22float2(a1);
                acc[qi] += (f0.x + f0.y) + (f1.x + f1.y);
            }
            ka = na; kb = nb;
        }
    }

    // ---- mask + stash scores ----
    const bool live = (kj < vlen);
#pragma unroll
    for (int qi = 0; qi < TQ; qi++)
        s_s[qi][kj] = live ? acc[qi] : -1e6f;
    __syncthreads();

    // ---- softmax: warp w handles row w (warps 0..TQ-1) ----
    const int w = tid >> 5, lane = tid & 31;
    if (w < TQ) {
        const int r = w;
        float vals[8];
        float vmax = -1e30f;
#pragma unroll
        for (int t = 0; t < 8; t++) {
            vals[t] = s_s[r][lane + t * 32];
            vmax = fmaxf(vmax, vals[t]);
        }
#pragma unroll
        for (int off = 16; off; off >>= 1)
            vmax = fmaxf(vmax, __shfl_xor_sync(0xFFFFFFFFu, vmax, off));
        float vsum = 0.f;
#pragma unroll
        for (int t = 0; t < 8; t++) {
            vals[t] = __expf(vals[t] - vmax);
            vsum += vals[t];
        }
#pragma unroll
        for (int off = 16; off; off >>= 1)
            vsum += __shfl_xor_sync(0xFFFFFFFFu, vsum, off);
        const float inv = 1.f / vsum;
#pragma unroll
        for (int t = 0; t < 8; t++)
            s_s[r][lane + t * 32] = vals[t] * inv;
    }
    __syncthreads();

    // ---- attn @ values: thread owns column d = tid ----
    // 8-wide v double-buffer (R12 structure); s_s rows read as float4;
    // k >= vlen skipped (attn weights there are exactly 0).
    const int d = tid;
    const int kend = (vlen + 7) & ~7;              // vlen >= 1 so kend >= 8
    const float* vb = values + b * KN * DN + d;
    float o[TQ];
#pragma unroll
    for (int i = 0; i < TQ; i++) o[i] = 0.f;

    float v[8], vn[8];
#pragma unroll
    for (int t = 0; t < 8; t++) v[t] = __ldg(vb + t * DN);

#pragma unroll 1
    for (int k = 0; k < kend; k += 8) {
        const int nk = (k + 8 < kend) ? k + 8 : k;
#pragma unroll
        for (int t = 0; t < 8; t++) vn[t] = __ldg(vb + (nk + t) * DN);
#pragma unroll
        for (int qi = 0; qi < TQ; qi++) {
            const float4 sa = *(const float4*)&s_s[qi][k];
            const float4 sb = *(const float4*)&s_s[qi][k + 4];
            o[qi] += sa.x * v[0] + sa.y * v[1] + sa.z * v[2] + sa.w * v[3]
                   + sb.x * v[4] + sb.y * v[5] + sb.z * v[6] + sb.w * v[7];
        }
#pragma unroll
        for (int t = 0; t < 8; t++) v[t] = vn[t];
    }
    float* ob = out + (b * QN + q0) * DN + d;
#pragma unroll
    for (int qi = 0; qi < TQ; qi++) ob[qi * DN] = o[qi];
}

// ---------------------------------------------------------------------------
extern "C" void kernel_launch(void* const* d_in, const int* in_sizes, int n_in,
                              void* d_out, int out_size)
{
    const float* queries = (const float*)d_in[0];
    const float* keys    = (const float*)d_in[1];
    const float* values  = (const float*)d_in[2];
    const int*   vlens   = (const int*)d_in[3];
    const float* Wq      = (const float*)d_in[4];
    const float* Wk      = (const float*)d_in[5];
    const float* wv      = (const float*)d_in[6];
    float*       out     = (float*)d_out;

    dim3 gA(32, 2, 2);               // (4096/128, 256/128, {q,k}) = 128 blocks
    proj_kernel<<<gA, 256>>>(queries, keys, Wq, Wk);

    dim3 gB(QN / TQ, BN);            // (64, 16) = 1024 blocks
    attn_kernel<<<gB, 256>>>(values, vlens, wv, out);
}

// round 15
// speedup vs baseline: 1.1567x; 1.0981x over previous
#include <cuda_runtime.h>
#include <cuda_fp16.h>
#include <cstdint>

#define BN 16
#define QN 256
#define KN 256
#define DN 256
#define HN 256
#define TQ 4
#define H2 (HN/2)

// scratch (device globals: no allocation allowed) — both projections half,
// row-major [row][h] with h contiguous (q row = (b,q), k row = (b,kj)).
__device__ __half g_qproj[BN * QN * HN];
__device__ __half g_kproj[BN * KN * HN];

__device__ __forceinline__ __half2 htanh2(__half2 x) {
    unsigned r, xi = *(unsigned*)&x;
    asm("tanh.approx.f16x2 %0, %1;" : "=r"(r) : "r"(xi));
    return *(__half2*)&r;
}

// ---------------------------------------------------------------------------
// Kernel A: dual projection GEMM on tensor cores (m16n8k16 f16, f32 accum).
// R15: block tile 128x64 -> 256 blocks, 2 resident/SM (was 128x128, 128
// blocks at 1/SM with a third of the chip idle). 8 warps of 32x32.
// Same K-loop order per output -> bit-identical results vs R8 proj.
// ---------------------------------------------------------------------------
__global__ void __launch_bounds__(256, 2) proj_kernel(
    const float* __restrict__ Aq, const float* __restrict__ Ak,
    const float* __restrict__ Wq, const float* __restrict__ Wk)
{
    const int z = blockIdx.z;
    const float* __restrict__ A = z ? Ak : Aq;
    const float* __restrict__ W = z ? Wk : Wq;
    __half* __restrict__ out = z ? g_kproj : g_qproj;

    __shared__ __half As[128 * 24];   // [row][k] stride 24
    __shared__ __half Bs[64 * 24];    // [n][k]   stride 24 (transposed W tile)

    const int tid  = threadIdx.x;
    const int wid  = tid >> 5, lane = tid & 31;
    const int m0   = blockIdx.x * 128;
    const int n0   = blockIdx.y * 64;
    const int wm   = (wid & 3) * 32;      // 4 warp-rows x 32 m
    const int wn   = (wid >> 2) * 32;     // 2 warp-cols x 32 n

    // loaders: A tile 128x16 (two float4/thread), B tile 16x64 (one float4)
    const int arow = tid >> 1, acol = (tid & 1) * 8;
    const int brow = tid >> 4, bcol = (tid & 15) * 4;

    const uint32_t as_base = (uint32_t)__cvta_generic_to_shared(As);
    const uint32_t bs_base = (uint32_t)__cvta_generic_to_shared(Bs);

    float4 a0v = *(const float4*)&A[(m0 + arow) * 256 + acol];
    float4 a1v = *(const float4*)&A[(m0 + arow) * 256 + acol + 4];
    float4 b0v = *(const float4*)&W[brow * 256 + n0 + bcol];

    float acc[2][4][4];
#pragma unroll
    for (int mi = 0; mi < 2; mi++)
#pragma unroll
        for (int ni = 0; ni < 4; ni++)
#pragma unroll
            for (int t = 0; t < 4; t++) acc[mi][ni][t] = 0.f;

#pragma unroll 1
    for (int ks = 0; ks < 16; ks++) {
        {
            __half2 ah[4];
            ah[0] = __floats2half2_rn(a0v.x, a0v.y);
            ah[1] = __floats2half2_rn(a0v.z, a0v.w);
            ah[2] = __floats2half2_rn(a1v.x, a1v.y);
            ah[3] = __floats2half2_rn(a1v.z, a1v.w);
            *(uint4*)&As[arow * 24 + acol] = *(uint4*)ah;

            float bfv[4] = {b0v.x, b0v.y, b0v.z, b0v.w};
#pragma unroll
            for (int j = 0; j < 4; j++)
                Bs[(bcol + j) * 24 + brow] = __float2half_rn(bfv[j]);
        }
        __syncthreads();

        if (ks < 15) {
            const int kk = (ks + 1) * 16;
            a0v = *(const float4*)&A[(m0 + arow) * 256 + kk + acol];
            a1v = *(const float4*)&A[(m0 + arow) * 256 + kk + acol + 4];
            b0v = *(const float4*)&W[(kk + brow) * 256 + n0 + bcol];
        }

        uint32_t af[2][4];
#pragma unroll
        for (int mi = 0; mi < 2; mi++) {
            uint32_t addr = as_base +
                ((wm + mi * 16 + (lane & 15)) * 24 + (lane >> 4) * 8) * 2;
            asm volatile(
                "ldmatrix.sync.aligned.m8n8.x4.shared.b16 {%0,%1,%2,%3}, [%4];"
                : "=r"(af[mi][0]), "=r"(af[mi][1]),
                  "=r"(af[mi][2]), "=r"(af[mi][3]) : "r"(addr));
        }
        uint32_t bf[4][2];
#pragma unroll
        for (int g = 0; g < 2; g++) {
            uint32_t addr = bs_base +
                ((wn + g * 16 + ((lane >> 4) << 3) + (lane & 7)) * 24 +
                 ((lane >> 3) & 1) * 8) * 2;
            uint32_t r0, r1, r2, r3;
            asm volatile(
                "ldmatrix.sync.aligned.m8n8.x4.shared.b16 {%0,%1,%2,%3}, [%4];"
                : "=r"(r0), "=r"(r1), "=r"(r2), "=r"(r3) : "r"(addr));
            bf[g * 2 + 0][0] = r0; bf[g * 2 + 0][1] = r1;
            bf[g * 2 + 1][0] = r2; bf[g * 2 + 1][1] = r3;
        }
#pragma unroll
        for (int mi = 0; mi < 2; mi++)
#pragma unroll
            for (int ni = 0; ni < 4; ni++) {
                asm volatile(
                    "mma.sync.aligned.m16n8k16.row.col.f32.f16.f16.f32 "
                    "{%0,%1,%2,%3}, {%4,%5,%6,%7}, {%8,%9}, {%0,%1,%2,%3};"
                    : "+f"(acc[mi][ni][0]), "+f"(acc[mi][ni][1]),
                      "+f"(acc[mi][ni][2]), "+f"(acc[mi][ni][3])
                    : "r"(af[mi][0]), "r"(af[mi][1]),
                      "r"(af[mi][2]), "r"(af[mi][3]),
                      "r"(bf[ni][0]), "r"(bf[ni][1]));
            }
        __syncthreads();
    }

#pragma unroll
    for (int mi = 0; mi < 2; mi++)
#pragma unroll
        for (int ni = 0; ni < 4; ni++) {
            const int row = m0 + wm + mi * 16 + (lane >> 2);
            const int col = n0 + wn + ni * 8 + (lane & 3) * 2;
            *(__half2*)&out[row * 256 + col] =
                __floats2half2_rn(acc[mi][ni][0], acc[mi][ni][1]);
            *(__half2*)&out[(row + 8) * 256 + col] =
                __floats2half2_rn(acc[mi][ni][2], acc[mi][ni][3]);
        }
}

// ---------------------------------------------------------------------------
// Kernel B: fused scores + mask + softmax + attn@V.  (EXACT R12 best config:
// launch_bounds(256,4), TQ=4, split fp16 accumulators, 8-wide AV buffer.)
// ---------------------------------------------------------------------------
__global__ void __launch_bounds__(256, 4) attn_kernel(
    const float* __restrict__ values, const int* __restrict__ vlens_i32,
    const float* __restrict__ wv, float* __restrict__ out)
{
    const int b  = blockIdx.y;
    const int q0 = blockIdx.x * TQ;
    const int tid = threadIdx.x;

    __shared__ __half2 q_s2[TQ][H2];                 // 2 KB
    __shared__ __align__(16) float s_s[TQ][KN];      // 4 KB
    __shared__ __half2 wv_s2[H2];                    // 0.5 KB

    // load q tile (already half) + wv
    const uint4* qbase = (const uint4*)(g_qproj + (b * QN + q0) * HN);
    for (int i = tid; i < TQ * H2 / 4; i += 256)
        ((uint4*)q_s2)[i] = qbase[i];
    for (int i = tid; i < H2; i += 256) {
        float2 v = ((const float2*)wv)[i];
        wv_s2[i] = __float22half2_rn(v);
    }
    __syncthreads();

    const int stride = (vlens_i32[1] == 0) ? 2 : 1;   // int64 vs int32 probe
    const int vlen = vlens_i32[b * stride];

    // ---- score phase: this thread owns column kj = tid ----
    const int kj = tid;
    float acc[TQ];
#pragma unroll
    for (int i = 0; i < TQ; i++) acc[i] = 0.f;

    if (kj < vlen) {
        const uint4* krow = (const uint4*)(g_kproj + (b * KN + kj) * HN);

        uint4 ka = __ldg(krow + 0), kb = __ldg(krow + 1);

#pragma unroll 1
        for (int c = 0; c < 32; c += 2) {            // 2 chunks (16 h) / iter
            const int nc = (c + 2 < 32) ? c + 2 : c;
            uint4 na = __ldg(krow + nc), nb = __ldg(krow + nc + 1);

            __half2 kva[4], kvb[4];
            kva[0] = *(__half2*)&ka.x; kva[1] = *(__half2*)&ka.y;
            kva[2] = *(__half2*)&ka.z; kva[3] = *(__half2*)&ka.w;
            kvb[0] = *(__half2*)&kb.x; kvb[1] = *(__half2*)&kb.y;
            kvb[2] = *(__half2*)&kb.z; kvb[3] = *(__half2*)&kb.w;

            const int hc2 = c * 4;
            __half2 wra[4], wrb[4];
#pragma unroll
            for (int t = 0; t < 4; t++) wra[t] = wv_s2[hc2 + t];
#pragma unroll
            for (int t = 0; t < 4; t++) wrb[t] = wv_s2[hc2 + 4 + t];

#pragma unroll
            for (int qi = 0; qi < TQ; qi++) {
                uint4 qra = *(const uint4*)&q_s2[qi][hc2];
                uint4 qrb = *(const uint4*)&q_s2[qi][hc2 + 4];
                __half2 qa[4], qb[4];
                qa[0] = *(__half2*)&qra.x; qa[1] = *(__half2*)&qra.y;
                qa[2] = *(__half2*)&qra.z; qa[3] = *(__half2*)&qra.w;
                qb[0] = *(__half2*)&qrb.x; qb[1] = *(__half2*)&qrb.y;
                qb[2] = *(__half2*)&qrb.z; qb[3] = *(__half2*)&qrb.w;

                // two independent fp16 accumulators -> half the HFMA2 chain
                __half2 a0 = __float2half2_rn(0.f);
                __half2 a1 = __float2half2_rn(0.f);
#pragma unroll
                for (int t = 0; t < 4; t++)
                    a0 = __hfma2(wra[t], htanh2(__hadd2(qa[t], kva[t])), a0);
#pragma unroll
                for (int t = 0; t < 4; t++)
                    a1 = __hfma2(wrb[t], htanh2(__hadd2(qb[t], kvb[t])), a1);
                float2 f0 = __half22float2(a0);
                float2 f1 = __half22float2(a1);
                acc[qi] += (f0.x + f0.y) + (f1.x + f1.y);
            }
            ka = na; kb = nb;
        }
    }

    // ---- mask + stash scores ----
    const bool live = (kj < vlen);
#pragma unroll
    for (int qi = 0; qi < TQ; qi++)
        s_s[qi][kj] = live ? acc[qi] : -1e6f;
    __syncthreads();

    // ---- softmax: warp w handles row w (warps 0..TQ-1) ----
    const int w = tid >> 5, lane = tid & 31;
    if (w < TQ) {
        const int r = w;
        float vals[8];
        float vmax = -1e30f;
#pragma unroll
        for (int t = 0; t < 8; t++) {
            vals[t] = s_s[r][lane + t * 32];
            vmax = fmaxf(vmax, vals[t]);
        }
#pragma unroll
        for (int off = 16; off; off >>= 1)
            vmax = fmaxf(vmax, __shfl_xor_sync(0xFFFFFFFFu, vmax, off));
        float vsum = 0.f;
#pragma unroll
        for (int t = 0; t < 8; t++) {
            vals[t] = __expf(vals[t] - vmax);
            vsum += vals[t];
        }
#pragma unroll
        for (int off = 16; off; off >>= 1)
            vsum += __shfl_xor_sync(0xFFFFFFFFu, vsum, off);
        const float inv = 1.f / vsum;
#pragma unroll
        for (int t = 0; t < 8; t++)
            s_s[r][lane + t * 32] = vals[t] * inv;
    }
    __syncthreads();

    // ---- attn @ values: thread owns column d = tid ----
    // 8-wide v double-buffer; s_s rows read as float4; k >= vlen skipped
    // (attn weights there are exactly 0).
    const int d = tid;
    const int kend = (vlen + 7) & ~7;              // vlen >= 1 so kend >= 8
    const float* vb = values + b * KN * DN + d;
    float o[TQ];
#pragma unroll
    for (int i = 0; i < TQ; i++) o[i] = 0.f;

    float v[8], vn[8];
#pragma unroll
    for (int t = 0; t < 8; t++) v[t] = __ldg(vb + t * DN);

#pragma unroll 1
    for (int k = 0; k < kend; k += 8) {
        const int nk = (k + 8 < kend) ? k + 8 : k;
#pragma unroll
        for (int t = 0; t < 8; t++) vn[t] = __ldg(vb + (nk + t) * DN);
#pragma unroll
        for (int qi = 0; qi < TQ; qi++) {
            const float4 sa = *(const float4*)&s_s[qi][k];
            const float4 sb = *(const float4*)&s_s[qi][k + 4];
            o[qi] += sa.x * v[0] + sa.y * v[1] + sa.z * v[2] + sa.w * v[3]
                   + sb.x * v[4] + sb.y * v[5] + sb.z * v[6] + sb.w * v[7];
        }
#pragma unroll
        for (int t = 0; t < 8; t++) v[t] = vn[t];
    }
    float* ob = out + (b * QN + q0) * DN + d;
#pragma unroll
    for (int qi = 0; qi < TQ; qi++) ob[qi * DN] = o[qi];
}

// ---------------------------------------------------------------------------
extern "C" void kernel_launch(void* const* d_in, const int* in_sizes, int n_in,
                              void* d_out, int out_size)
{
    const float* queries = (const float*)d_in[0];
    const float* keys    = (const float*)d_in[1];
    const float* values  = (const float*)d_in[2];
    const int*   vlens   = (const int*)d_in[3];
    const float* Wq      = (const float*)d_in[4];
    const float* Wk      = (const float*)d_in[5];
    const float* wv      = (const float*)d_in[6];
    float*       out     = (float*)d_out;

    dim3 gA(32, 4, 2);               // (4096/128, 256/64, {q,k}) = 256 blocks
    proj_kernel<<<gA, 256>>>(queries, keys, Wq, Wk);

    dim3 gB(QN / TQ, BN);            // (64, 16) = 1024 blocks
    attn_kernel<<<gB, 256>>>(values, vlens, wv, out);
}

// round 16
// speedup vs baseline: 1.1881x; 1.0271x over previous
#include <cuda_runtime.h>
#include <cuda_fp16.h>
#include <cstdint>

#define BN 16
#define QN 256
#define KN 256
#define DN 256
#define HN 256
#define TQ 4
#define H2 (HN/2)

// scratch (device globals: no allocation allowed) — both projections half,
// row-major [row][h] with h contiguous (q row = (b,q), k row = (b,kj)).
__device__ __half g_qproj[BN * QN * HN];
__device__ __half g_kproj[BN * KN * HN];
__device__ int    g_perm[BN];            // batches sorted by vlen descending

__device__ __forceinline__ __half2 htanh2(__half2 x) {
    unsigned r, xi = *(unsigned*)&x;
    asm("tanh.approx.f16x2 %0, %1;" : "=r"(r) : "r"(xi));
    return *(__half2*)&r;
}

// ---------------------------------------------------------------------------
// Kernel 0: LPT prep — sort batch ids by vlen descending (deterministic,
// index tie-break). 16 elements, one thread.
// ---------------------------------------------------------------------------
__global__ void prep_kernel(const int* __restrict__ vlens_i32) {
    if (threadIdx.x == 0) {
        const int stride = (vlens_i32[1] == 0) ? 2 : 1;
        int vl[BN];
        bool used[BN];
#pragma unroll
        for (int i = 0; i < BN; i++) { vl[i] = vlens_i32[i * stride]; used[i] = false; }
        for (int r = 0; r < BN; r++) {
            int best = -1, bi = 0;
            for (int i = 0; i < BN; i++)
                if (!used[i] && vl[i] > best) { best = vl[i]; bi = i; }
            used[bi] = true;
            g_perm[r] = bi;
        }
    }
}

// ---------------------------------------------------------------------------
// Kernel A: dual projection GEMM on tensor cores (m16n8k16 f16, f32 accum).
// Block tile 128x64 -> 256 blocks, 2 resident/SM. (unchanged — verified R15)
// ---------------------------------------------------------------------------
__global__ void __launch_bounds__(256, 2) proj_kernel(
    const float* __restrict__ Aq, const float* __restrict__ Ak,
    const float* __restrict__ Wq, const float* __restrict__ Wk)
{
    const int z = blockIdx.z;
    const float* __restrict__ A = z ? Ak : Aq;
    const float* __restrict__ W = z ? Wk : Wq;
    __half* __restrict__ out = z ? g_kproj : g_qproj;

    __shared__ __half As[128 * 24];   // [row][k] stride 24
    __shared__ __half Bs[64 * 24];    // [n][k]   stride 24 (transposed W tile)

    const int tid  = threadIdx.x;
    const int wid  = tid >> 5, lane = tid & 31;
    const int m0   = blockIdx.x * 128;
    const int n0   = blockIdx.y * 64;
    const int wm   = (wid & 3) * 32;
    const int wn   = (wid >> 2) * 32;

    const int arow = tid >> 1, acol = (tid & 1) * 8;
    const int brow = tid >> 4, bcol = (tid & 15) * 4;

    const uint32_t as_base = (uint32_t)__cvta_generic_to_shared(As);
    const uint32_t bs_base = (uint32_t)__cvta_generic_to_shared(Bs);

    float4 a0v = *(const float4*)&A[(m0 + arow) * 256 + acol];
    float4 a1v = *(const float4*)&A[(m0 + arow) * 256 + acol + 4];
    float4 b0v = *(const float4*)&W[brow * 256 + n0 + bcol];

    float acc[2][4][4];
#pragma unroll
    for (int mi = 0; mi < 2; mi++)
#pragma unroll
        for (int ni = 0; ni < 4; ni++)
#pragma unroll
            for (int t = 0; t < 4; t++) acc[mi][ni][t] = 0.f;

#pragma unroll 1
    for (int ks = 0; ks < 16; ks++) {
        {
            __half2 ah[4];
            ah[0] = __floats2half2_rn(a0v.x, a0v.y);
            ah[1] = __floats2half2_rn(a0v.z, a0v.w);
            ah[2] = __floats2half2_rn(a1v.x, a1v.y);
            ah[3] = __floats2half2_rn(a1v.z, a1v.w);
            *(uint4*)&As[arow * 24 + acol] = *(uint4*)ah;

            float bfv[4] = {b0v.x, b0v.y, b0v.z, b0v.w};
#pragma unroll
            for (int j = 0; j < 4; j++)
                Bs[(bcol + j) * 24 + brow] = __float2half_rn(bfv[j]);
        }
        __syncthreads();

        if (ks < 15) {
            const int kk = (ks + 1) * 16;
            a0v = *(const float4*)&A[(m0 + arow) * 256 + kk + acol];
            a1v = *(const float4*)&A[(m0 + arow) * 256 + kk + acol + 4];
            b0v = *(const float4*)&W[(kk + brow) * 256 + n0 + bcol];
        }

        uint32_t af[2][4];
#pragma unroll
        for (int mi = 0; mi < 2; mi++) {
            uint32_t addr = as_base +
                ((wm + mi * 16 + (lane & 15)) * 24 + (lane >> 4) * 8) * 2;
            asm volatile(
                "ldmatrix.sync.aligned.m8n8.x4.shared.b16 {%0,%1,%2,%3}, [%4];"
                : "=r"(af[mi][0]), "=r"(af[mi][1]),
                  "=r"(af[mi][2]), "=r"(af[mi][3]) : "r"(addr));
        }
        uint32_t bf[4][2];
#pragma unroll
        for (int g = 0; g < 2; g++) {
            uint32_t addr = bs_base +
                ((wn + g * 16 + ((lane >> 4) << 3) + (lane & 7)) * 24 +
                 ((lane >> 3) & 1) * 8) * 2;
            uint32_t r0, r1, r2, r3;
            asm volatile(
                "ldmatrix.sync.aligned.m8n8.x4.shared.b16 {%0,%1,%2,%3}, [%4];"
                : "=r"(r0), "=r"(r1), "=r"(r2), "=r"(r3) : "r"(addr));
            bf[g * 2 + 0][0] = r0; bf[g * 2 + 0][1] = r1;
            bf[g * 2 + 1][0] = r2; bf[g * 2 + 1][1] = r3;
        }
#pragma unroll
        for (int mi = 0; mi < 2; mi++)
#pragma unroll
            for (int ni = 0; ni < 4; ni++) {
                asm volatile(
                    "mma.sync.aligned.m16n8k16.row.col.f32.f16.f16.f32 "
                    "{%0,%1,%2,%3}, {%4,%5,%6,%7}, {%8,%9}, {%0,%1,%2,%3};"
                    : "+f"(acc[mi][ni][0]), "+f"(acc[mi][ni][1]),
                      "+f"(acc[mi][ni][2]), "+f"(acc[mi][ni][3])
                    : "r"(af[mi][0]), "r"(af[mi][1]),
                      "r"(af[mi][2]), "r"(af[mi][3]),
                      "r"(bf[ni][0]), "r"(bf[ni][1]));
            }
        __syncthreads();
    }

#pragma unroll
    for (int mi = 0; mi < 2; mi++)
#pragma unroll
        for (int ni = 0; ni < 4; ni++) {
            const int row = m0 + wm + mi * 16 + (lane >> 2);
            const int col = n0 + wn + ni * 8 + (lane & 3) * 2;
            *(__half2*)&out[row * 256 + col] =
                __floats2half2_rn(acc[mi][ni][0], acc[mi][ni][1]);
            *(__half2*)&out[(row + 8) * 256 + col] =
                __floats2half2_rn(acc[mi][ni][2], acc[mi][ni][3]);
        }
}

// ---------------------------------------------------------------------------
// Kernel B: fused scores + mask + softmax + attn@V.  R12 best config
// (launch_bounds(256,4), TQ=4, 8-wide AV buffer) + R16 changes: LPT batch
// order via g_perm; HADD2 accumulator combine before f32 promote.
// ---------------------------------------------------------------------------
__global__ void __launch_bounds__(256, 4) attn_kernel(
    const float* __restrict__ values, const int* __restrict__ vlens_i32,
    const float* __restrict__ wv, float* __restrict__ out)
{
    const int b  = g_perm[blockIdx.y];               // LPT: big vlen first
    const int q0 = blockIdx.x * TQ;
    const int tid = threadIdx.x;

    __shared__ __half2 q_s2[TQ][H2];                 // 2 KB
    __shared__ __align__(16) float s_s[TQ][KN];      // 4 KB
    __shared__ __half2 wv_s2[H2];                    // 0.5 KB

    // load q tile (already half) + wv
    const uint4* qbase = (const uint4*)(g_qproj + (b * QN + q0) * HN);
    for (int i = tid; i < TQ * H2 / 4; i += 256)
        ((uint4*)q_s2)[i] = qbase[i];
    for (int i = tid; i < H2; i += 256) {
        float2 v = ((const float2*)wv)[i];
        wv_s2[i] = __float22half2_rn(v);
    }
    __syncthreads();

    const int stride = (vlens_i32[1] == 0) ? 2 : 1;   // int64 vs int32 probe
    const int vlen = vlens_i32[b * stride];

    // ---- score phase: this thread owns column kj = tid ----
    const int kj = tid;
    float acc[TQ];
#pragma unroll
    for (int i = 0; i < TQ; i++) acc[i] = 0.f;

    if (kj < vlen) {
        const uint4* krow = (const uint4*)(g_kproj + (b * KN + kj) * HN);

        uint4 ka = __ldg(krow + 0), kb = __ldg(krow + 1);

#pragma unroll 1
        for (int c = 0; c < 32; c += 2) {            // 2 chunks (16 h) / iter
            const int nc = (c + 2 < 32) ? c + 2 : c;
            uint4 na = __ldg(krow + nc), nb = __ldg(krow + nc + 1);

            __half2 kva[4], kvb[4];
            kva[0] = *(__half2*)&ka.x; kva[1] = *(__half2*)&ka.y;
            kva[2] = *(__half2*)&ka.z; kva[3] = *(__half2*)&ka.w;
            kvb[0] = *(__half2*)&kb.x; kvb[1] = *(__half2*)&kb.y;
            kvb[2] = *(__half2*)&kb.z; kvb[3] = *(__half2*)&kb.w;

            const int hc2 = c * 4;
            __half2 wra[4], wrb[4];
#pragma unroll
            for (int t = 0; t < 4; t++) wra[t] = wv_s2[hc2 + t];
#pragma unroll
            for (int t = 0; t < 4; t++) wrb[t] = wv_s2[hc2 + 4 + t];

#pragma unroll
            for (int qi = 0; qi < TQ; qi++) {
                uint4 qra = *(const uint4*)&q_s2[qi][hc2];
                uint4 qrb = *(const uint4*)&q_s2[qi][hc2 + 4];
                __half2 qa[4], qb[4];
                qa[0] = *(__half2*)&qra.x; qa[1] = *(__half2*)&qra.y;
                qa[2] = *(__half2*)&qra.z; qa[3] = *(__half2*)&qra.w;
                qb[0] = *(__half2*)&qrb.x; qb[1] = *(__half2*)&qrb.y;
                qb[2] = *(__half2*)&qrb.z; qb[3] = *(__half2*)&qrb.w;

                // two independent fp16 accumulators -> half the HFMA2 chain
                __half2 a0 = __float2half2_rn(0.f);
                __half2 a1 = __float2half2_rn(0.f);
#pragma unroll
                for (int t = 0; t < 4; t++)
                    a0 = __hfma2(wra[t], htanh2(__hadd2(qa[t], kva[t])), a0);
#pragma unroll
                for (int t = 0; t < 4; t++)
                    a1 = __hfma2(wrb[t], htanh2(__hadd2(qb[t], kvb[t])), a1);
                // combine in half first (1 HADD2), then single promote
                float2 f = __half22float2(__hadd2(a0, a1));
                acc[qi] += f.x + f.y;
            }
            ka = na; kb = nb;
        }
    }

    // ---- mask + stash scores ----
    const bool live = (kj < vlen);
#pragma unroll
    for (int qi = 0; qi < TQ; qi++)
        s_s[qi][kj] = live ? acc[qi] : -1e6f;
    __syncthreads();

    // ---- softmax: warp w handles row w (warps 0..TQ-1) ----
    const int w = tid >> 5, lane = tid & 31;
    if (w < TQ) {
        const int r = w;
        float vals[8];
        float vmax = -1e30f;
#pragma unroll
        for (int t = 0; t < 8; t++) {
            vals[t] = s_s[r][lane + t * 32];
            vmax = fmaxf(vmax, vals[t]);
        }
#pragma unroll
        for (int off = 16; off; off >>= 1)
            vmax = fmaxf(vmax, __shfl_xor_sync(0xFFFFFFFFu, vmax, off));
        float vsum = 0.f;
#pragma unroll
        for (int t = 0; t < 8; t++) {
            vals[t] = __expf(vals[t] - vmax);
            vsum += vals[t];
        }
#pragma unroll
        for (int off = 16; off; off >>= 1)
            vsum += __shfl_xor_sync(0xFFFFFFFFu, vsum, off);
        const float inv = 1.f / vsum;
#pragma unroll
        for (int t = 0; t < 8; t++)
            s_s[r][lane + t * 32] = vals[t] * inv;
    }
    __syncthreads();

    // ---- attn @ values: thread owns column d = tid ----
    // 8-wide v double-buffer; s_s rows read as float4; k >= vlen skipped
    // (attn weights there are exactly 0).
    const int d = tid;
    const int kend = (vlen + 7) & ~7;              // vlen >= 1 so kend >= 8
    const float* vb = values + b * KN * DN + d;
    float o[TQ];
#pragma unroll
    for (int i = 0; i < TQ; i++) o[i] = 0.f;

    float v[8], vn[8];
#pragma unroll
    for (int t = 0; t < 8; t++) v[t] = __ldg(vb + t * DN);

#pragma unroll 1
    for (int k = 0; k < kend; k += 8) {
        const int nk = (k + 8 < kend) ? k + 8 : k;
#pragma unroll
        for (int t = 0; t < 8; t++) vn[t] = __ldg(vb + (nk + t) * DN);
#pragma unroll
        for (int qi = 0; qi < TQ; qi++) {
            const float4 sa = *(const float4*)&s_s[qi][k];
            const float4 sb = *(const float4*)&s_s[qi][k + 4];
            o[qi] += sa.x * v[0] + sa.y * v[1] + sa.z * v[2] + sa.w * v[3]
                   + sb.x * v[4] + sb.y * v[5] + sb.z * v[6] + sb.w * v[7];
        }
#pragma unroll
        for (int t = 0; t < 8; t++) v[t] = vn[t];
    }
    float* ob = out + (b * QN + q0) * DN + d;
#pragma unroll
    for (int qi = 0; qi < TQ; qi++) ob[qi * DN] = o[qi];
}

// ---------------------------------------------------------------------------
extern "C" void kernel_launch(void* const* d_in, const int* in_sizes, int n_in,
                              void* d_out, int out_size)
{
    const float* queries = (const float*)d_in[0];
    const float* keys    = (const float*)d_in[1];
    const float* values  = (const float*)d_in[2];
    const int*   vlens   = (const int*)d_in[3];
    const float* Wq      = (const float*)d_in[4];
    const float* Wk      = (const float*)d_in[5];
    const float* wv      = (const float*)d_in[6];
    float*       out     = (float*)d_out;

    prep_kernel<<<1, 32>>>(vlens);

    dim3 gA(32, 4, 2);               // (4096/128, 256/64, {q,k}) = 256 blocks
    proj_kernel<<<gA, 256>>>(queries, keys, Wq, Wk);

    dim3 gB(QN / TQ, BN);            // (64, 16) = 1024 blocks
    attn_kernel<<<gB, 256>>>(values, vlens, wv, out);
}

// round 17
// speedup vs baseline: 1.2332x; 1.0380x over previous
#include <cuda_runtime.h>
#include <cuda_fp16.h>
#include <cstdint>

#define BN 16
#define QN 256
#define KN 256
#define DN 256
#define HN 256
#define TQ 4
#define H2 (HN/2)

// scratch (device globals: no allocation allowed) — both projections half,
// row-major [row][h] with h contiguous (q row = (b,q), k row = (b,kj)).
__device__ __half g_qproj[BN * QN * HN];
__device__ __half g_kproj[BN * KN * HN];

__device__ __forceinline__ __half2 htanh2(__half2 x) {
    unsigned r, xi = *(unsigned*)&x;
    asm("tanh.approx.f16x2 %0, %1;" : "=r"(r) : "r"(xi));
    return *(__half2*)&r;
}

// ---------------------------------------------------------------------------
// Kernel A: dual projection GEMM on tensor cores (m16n8k16 f16, f32 accum).
// Block tile 128x64 -> 256 blocks, 2 resident/SM. (unchanged — verified R15)
// ---------------------------------------------------------------------------
__global__ void __launch_bounds__(256, 2) proj_kernel(
    const float* __restrict__ Aq, const float* __restrict__ Ak,
    const float* __restrict__ Wq, const float* __restrict__ Wk)
{
    const int z = blockIdx.z;
    const float* __restrict__ A = z ? Ak : Aq;
    const float* __restrict__ W = z ? Wk : Wq;
    __half* __restrict__ out = z ? g_kproj : g_qproj;

    __shared__ __half As[128 * 24];   // [row][k] stride 24
    __shared__ __half Bs[64 * 24];    // [n][k]   stride 24 (transposed W tile)

    const int tid  = threadIdx.x;
    const int wid  = tid >> 5, lane = tid & 31;
    const int m0   = blockIdx.x * 128;
    const int n0   = blockIdx.y * 64;
    const int wm   = (wid & 3) * 32;
    const int wn   = (wid >> 2) * 32;

    const int arow = tid >> 1, acol = (tid & 1) * 8;
    const int brow = tid >> 4, bcol = (tid & 15) * 4;

    const uint32_t as_base = (uint32_t)__cvta_generic_to_shared(As);
    const uint32_t bs_base = (uint32_t)__cvta_generic_to_shared(Bs);

    float4 a0v = *(const float4*)&A[(m0 + arow) * 256 + acol];
    float4 a1v = *(const float4*)&A[(m0 + arow) * 256 + acol + 4];
    float4 b0v = *(const float4*)&W[brow * 256 + n0 + bcol];

    float acc[2][4][4];
#pragma unroll
    for (int mi = 0; mi < 2; mi++)
#pragma unroll
        for (int ni = 0; ni < 4; ni++)
#pragma unroll
            for (int t = 0; t < 4; t++) acc[mi][ni][t] = 0.f;

#pragma unroll 1
    for (int ks = 0; ks < 16; ks++) {
        {
            __half2 ah[4];
            ah[0] = __floats2half2_rn(a0v.x, a0v.y);
            ah[1] = __floats2half2_rn(a0v.z, a0v.w);
            ah[2] = __floats2half2_rn(a1v.x, a1v.y);
            ah[3] = __floats2half2_rn(a1v.z, a1v.w);
            *(uint4*)&As[arow * 24 + acol] = *(uint4*)ah;

            float bfv[4] = {b0v.x, b0v.y, b0v.z, b0v.w};
#pragma unroll
            for (int j = 0; j < 4; j++)
                Bs[(bcol + j) * 24 + brow] = __float2half_rn(bfv[j]);
        }
        __syncthreads();

        if (ks < 15) {
            const int kk = (ks + 1) * 16;
            a0v = *(const float4*)&A[(m0 + arow) * 256 + kk + acol];
            a1v = *(const float4*)&A[(m0 + arow) * 256 + kk + acol + 4];
            b0v = *(const float4*)&W[(kk + brow) * 256 + n0 + bcol];
        }

        uint32_t af[2][4];
#pragma unroll
        for (int mi = 0; mi < 2; mi++) {
            uint32_t addr = as_base +
                ((wm + mi * 16 + (lane & 15)) * 24 + (lane >> 4) * 8) * 2;
            asm volatile(
                "ldmatrix.sync.aligned.m8n8.x4.shared.b16 {%0,%1,%2,%3}, [%4];"
                : "=r"(af[mi][0]), "=r"(af[mi][1]),
                  "=r"(af[mi][2]), "=r"(af[mi][3]) : "r"(addr));
        }
        uint32_t bf[4][2];
#pragma unroll
        for (int g = 0; g < 2; g++) {
            uint32_t addr = bs_base +
                ((wn + g * 16 + ((lane >> 4) << 3) + (lane & 7)) * 24 +
                 ((lane >> 3) & 1) * 8) * 2;
            uint32_t r0, r1, r2, r3;
            asm volatile(
                "ldmatrix.sync.aligned.m8n8.x4.shared.b16 {%0,%1,%2,%3}, [%4];"
                : "=r"(r0), "=r"(r1), "=r"(r2), "=r"(r3) : "r"(addr));
            bf[g * 2 + 0][0] = r0; bf[g * 2 + 0][1] = r1;
            bf[g * 2 + 1][0] = r2; bf[g * 2 + 1][1] = r3;
        }
#pragma unroll
        for (int mi = 0; mi < 2; mi++)
#pragma unroll
            for (int ni = 0; ni < 4; ni++) {
                asm volatile(
                    "mma.sync.aligned.m16n8k16.row.col.f32.f16.f16.f32 "
                    "{%0,%1,%2,%3}, {%4,%5,%6,%7}, {%8,%9}, {%0,%1,%2,%3};"
                    : "+f"(acc[mi][ni][0]), "+f"(acc[mi][ni][1]),
                      "+f"(acc[mi][ni][2]), "+f"(acc[mi][ni][3])
                    : "r"(af[mi][0]), "r"(af[mi][1]),
                      "r"(af[mi][2]), "r"(af[mi][3]),
                      "r"(bf[ni][0]), "r"(bf[ni][1]));
            }
        __syncthreads();
    }

#pragma unroll
    for (int mi = 0; mi < 2; mi++)
#pragma unroll
        for (int ni = 0; ni < 4; ni++) {
            const int row = m0 + wm + mi * 16 + (lane >> 2);
            const int col = n0 + wn + ni * 8 + (lane & 3) * 2;
            *(__half2*)&out[row * 256 + col] =
                __floats2half2_rn(acc[mi][ni][0], acc[mi][ni][1]);
            *(__half2*)&out[(row + 8) * 256 + col] =
                __floats2half2_rn(acc[mi][ni][2], acc[mi][ni][3]);
        }
}

// ---------------------------------------------------------------------------
// Kernel B: fused scores + mask + softmax + attn@V.  R12 best config
// (launch_bounds(256,4), TQ=4, 8-wide AV buffer) + LPT batch order computed
// INLINE (warp-parallel rank; replaces the 6us prep kernel) + HADD2 combine.
// ---------------------------------------------------------------------------
__global__ void __launch_bounds__(256, 4) attn_kernel(
    const float* __restrict__ values, const int* __restrict__ vlens_i32,
    const float* __restrict__ wv, float* __restrict__ out)
{
    const int tid  = threadIdx.x;
    const int lane = tid & 31;

    // ---- inline LPT: b = batch with blockIdx.y-th largest vlen ----
    // Lanes 0..15 own batch i = lane; descending rank with index tie-break
    // (identical ordering to a stable selection sort by (vlen desc, idx asc)).
    const int stride = (__ldg(&vlens_i32[1]) == 0) ? 2 : 1; // int64/int32 probe
    const int i16  = lane & 15;
    const int vli  = __ldg(&vlens_i32[i16 * stride]);
    int rank = 0;
#pragma unroll
    for (int j = 0; j < BN; j++) {
        const int vlj = __shfl_sync(0xFFFFFFFFu, vli, j);
        rank += (vlj > vli) || (vlj == vli && j < i16);
    }
    const unsigned m =
        __ballot_sync(0xFFFFFFFFu, (rank == (int)blockIdx.y) && (lane < 16));
    const int b = __ffs(m) - 1;                      // uniform across block

    const int q0 = blockIdx.x * TQ;

    __shared__ __half2 q_s2[TQ][H2];                 // 2 KB
    __shared__ __align__(16) float s_s[TQ][KN];      // 4 KB
    __shared__ __half2 wv_s2[H2];                    // 0.5 KB

    // load q tile (already half) + wv
    const uint4* qbase = (const uint4*)(g_qproj + (b * QN + q0) * HN);
    for (int i = tid; i < TQ * H2 / 4; i += 256)
        ((uint4*)q_s2)[i] = qbase[i];
    for (int i = tid; i < H2; i += 256) {
        float2 v = ((const float2*)wv)[i];
        wv_s2[i] = __float22half2_rn(v);
    }
    __syncthreads();

    const int vlen = __shfl_sync(0xFFFFFFFFu, vli, b & 15); // vlen of batch b

    // ---- score phase: this thread owns column kj = tid ----
    const int kj = tid;
    float acc[TQ];
#pragma unroll
    for (int i = 0; i < TQ; i++) acc[i] = 0.f;

    if (kj < vlen) {
        const uint4* krow = (const uint4*)(g_kproj + (b * KN + kj) * HN);

        uint4 ka = __ldg(krow + 0), kb = __ldg(krow + 1);

#pragma unroll 1
        for (int c = 0; c < 32; c += 2) {            // 2 chunks (16 h) / iter
            const int nc = (c + 2 < 32) ? c + 2 : c;
            uint4 na = __ldg(krow + nc), nb = __ldg(krow + nc + 1);

            __half2 kva[4], kvb[4];
            kva[0] = *(__half2*)&ka.x; kva[1] = *(__half2*)&ka.y;
            kva[2] = *(__half2*)&ka.z; kva[3] = *(__half2*)&ka.w;
            kvb[0] = *(__half2*)&kb.x; kvb[1] = *(__half2*)&kb.y;
            kvb[2] = *(__half2*)&kb.z; kvb[3] = *(__half2*)&kb.w;

            const int hc2 = c * 4;
            __half2 wra[4], wrb[4];
#pragma unroll
            for (int t = 0; t < 4; t++) wra[t] = wv_s2[hc2 + t];
#pragma unroll
            for (int t = 0; t < 4; t++) wrb[t] = wv_s2[hc2 + 4 + t];

#pragma unroll
            for (int qi = 0; qi < TQ; qi++) {
                uint4 qra = *(const uint4*)&q_s2[qi][hc2];
                uint4 qrb = *(const uint4*)&q_s2[qi][hc2 + 4];
                __half2 qa[4], qb[4];
                qa[0] = *(__half2*)&qra.x; qa[1] = *(__half2*)&qra.y;
                qa[2] = *(__half2*)&qra.z; qa[3] = *(__half2*)&qra.w;
                qb[0] = *(__half2*)&qrb.x; qb[1] = *(__half2*)&qrb.y;
                qb[2] = *(__half2*)&qrb.z; qb[3] = *(__half2*)&qrb.w;

                // two independent fp16 accumulators -> half the HFMA2 chain
                __half2 a0 = __float2half2_rn(0.f);
                __half2 a1 = __float2half2_rn(0.f);
#pragma unroll
                for (int t = 0; t < 4; t++)
                    a0 = __hfma2(wra[t], htanh2(__hadd2(qa[t], kva[t])), a0);
#pragma unroll
                for (int t = 0; t < 4; t++)
                    a1 = __hfma2(wrb[t], htanh2(__hadd2(qb[t], kvb[t])), a1);
                // combine in half first (1 HADD2), then single promote
                float2 f = __half22float2(__hadd2(a0, a1));
                acc[qi] += f.x + f.y;
            }
            ka = na; kb = nb;
        }
    }

    // ---- mask + stash scores ----
    const bool live = (kj < vlen);
#pragma unroll
    for (int qi = 0; qi < TQ; qi++)
        s_s[qi][kj] = live ? acc[qi] : -1e6f;
    __syncthreads();

    // ---- softmax: warp w handles row w (warps 0..TQ-1) ----
    const int w = tid >> 5;
    if (w < TQ) {
        const int r = w;
        float vals[8];
        float vmax = -1e30f;
#pragma unroll
        for (int t = 0; t < 8; t++) {
            vals[t] = s_s[r][lane + t * 32];
            vmax = fmaxf(vmax, vals[t]);
        }
#pragma unroll
        for (int off = 16; off; off >>= 1)
            vmax = fmaxf(vmax, __shfl_xor_sync(0xFFFFFFFFu, vmax, off));
        float vsum = 0.f;
#pragma unroll
        for (int t = 0; t < 8; t++) {
            vals[t] = __expf(vals[t] - vmax);
            vsum += vals[t];
        }
#pragma unroll
        for (int off = 16; off; off >>= 1)
            vsum += __shfl_xor_sync(0xFFFFFFFFu, vsum, off);
        const float inv = 1.f / vsum;
#pragma unroll
        for (int t = 0; t < 8; t++)
            s_s[r][lane + t * 32] = vals[t] * inv;
    }
    __syncthreads();

    // ---- attn @ values: thread owns column d = tid ----
    // 8-wide v double-buffer; s_s rows read as float4; k >= vlen skipped
    // (attn weights there are exactly 0).
    const int d = tid;
    const int kend = (vlen + 7) & ~7;              // vlen >= 1 so kend >= 8
    const float* vb = values + b * KN * DN + d;
    float o[TQ];
#pragma unroll
    for (int i = 0; i < TQ; i++) o[i] = 0.f;

    float v[8], vn[8];
#pragma unroll
    for (int t = 0; t < 8; t++) v[t] = __ldg(vb + t * DN);

#pragma unroll 1
    for (int k = 0; k < kend; k += 8) {
        const int nk = (k + 8 < kend) ? k + 8 : k;
#pragma unroll
        for (int t = 0; t < 8; t++) vn[t] = __ldg(vb + (nk + t) * DN);
#pragma unroll
        for (int qi = 0; qi < TQ; qi++) {
            const float4 sa = *(const float4*)&s_s[qi][k];
            const float4 sb = *(const float4*)&s_s[qi][k + 4];
            o[qi] += sa.x * v[0] + sa.y * v[1] + sa.z * v[2] + sa.w * v[3]
                   + sb.x * v[4] + sb.y * v[5] + sb.z * v[6] + sb.w * v[7];
        }
#pragma unroll
        for (int t = 0; t < 8; t++) v[t] = vn[t];
    }
    float* ob = out + (b * QN + q0) * DN + d;
#pragma unroll
    for (int qi = 0; qi < TQ; qi++) ob[qi * DN] = o[qi];
}

// ---------------------------------------------------------------------------
extern "C" void kernel_launch(void* const* d_in, const int* in_sizes, int n_in,
                              void* d_out, int out_size)
{
    const float* queries = (const float*)d_in[0];
    const float* keys    = (const float*)d_in[1];
    const float* values  = (const float*)d_in[2];
    const int*   vlens   = (const int*)d_in[3];
    const float* Wq      = (const float*)d_in[4];
    const float* Wk      = (const float*)d_in[5];
    const float* wv      = (const float*)d_in[6];
    float*       out     = (float*)d_out;

    dim3 gA(32, 4, 2);               // (4096/128, 256/64, {q,k}) = 256 blocks
    proj_kernel<<<gA, 256>>>(queries, keys, Wq, Wk);

    dim3 gB(QN / TQ, BN);            // (64, 16) = 1024 blocks
    attn_kernel<<<gB, 256>>>(values, vlens, wv, out);
}